// round 12
// baseline (speedup 1.0000x reference)
#include <cuda_runtime.h>

#define NDIM 128
#define PLANE 16384          // 128*128
#define CS 2097152           // 128^3 (channel stride)
#define TVX 16
#define TVY 8
#define ZC 32
#define ROWL 18              // TVX+2
#define COLH 10              // TVY+2
#define NSLOT (ROWL*COLH)    // 180 per volume
#define VSTR 208             // smem stride between volumes (==16 mod 32)
#define PBUF (2*VSTR)        // one plane buffer (2 volumes) = 416
#define PAIR (2*PBUF)        // one 2-plane pair = 832
#define TOTSLOT (2*NSLOT)    // 360
#define NTHREADS 256
#define NBLOCKS 1024         // 8 * 16 * 8

__device__ double g_acc;          // zero-init at load; self-resetting
__device__ unsigned int g_cnt;    // ditto

// 7 2D-filtered values from a halo plane in smem.
// s=[1,2,1], d=[-1,0,1], o=[1,1,1]
// H[0]=s_y d_x  H[1]=d_y s_x  H[2]=o_y d_x  H[3]=d_y o_x
// H[4]=s_y s_x  H[5]=o_y s_x  H[6]=s_y o_x
__device__ __forceinline__ void computeH(const float* __restrict__ sm,
                                         int base, float* H) {
    const float* r0 = sm + base;
    const float* r1 = r0 + ROWL;
    const float* r2 = r1 + ROWL;
    float a00 = r0[0], a01 = r0[1], a02 = r0[2];
    float a10 = r1[0], a11 = r1[1], a12 = r1[2];
    float a20 = r2[0], a21 = r2[1], a22 = r2[2];
    float t0 = a00 + a20, t1 = a01 + a21, t2 = a02 + a22;
    float sc0 = fmaf(2.f, a10, t0), sc1 = fmaf(2.f, a11, t1), sc2 = fmaf(2.f, a12, t2);
    float oc0 = t0 + a10, oc1 = t1 + a11, oc2 = t2 + a12;
    float dc0 = a20 - a00, dc1 = a21 - a01, dc2 = a22 - a02;
    float td = dc0 + dc2, ts = sc0 + sc2, to = oc0 + oc2;
    H[0] = sc2 - sc0;
    H[1] = fmaf(2.f, dc1, td);
    H[2] = oc2 - oc0;
    H[3] = td + dc1;
    H[4] = fmaf(2.f, sc1, ts);
    H[5] = fmaf(2.f, oc1, to);
    H[6] = ts + sc1;
}

// Combine z-ring (A=z-1, B=z, C=z+1) into edge magnitude * 0.5 (C=2 channels).
__device__ __forceinline__ float edgeFromH(const float* A, const float* B, const float* C) {
    float t;
    t = A[0] + C[0];
    float Gssd = fmaf(2.f, B[0], t);
    float Gosd = t + B[0];
    t = A[1] + C[1];
    float Gsds = fmaf(2.f, B[1], t);
    float Gods = t + B[1];
    t = A[2] + C[2];
    float Gsod = fmaf(2.f, B[2], t);
    t = A[3] + C[3];
    float Gsdo = fmaf(2.f, B[3], t);
    float Gdss = C[4] - A[4];
    float Gdos = C[5] - A[5];
    float Gdso = C[6] - A[6];
    float s1 = Gssd * Gssd;
    s1 = fmaf(Gsds, Gsds, s1);
    s1 = fmaf(Gdss, Gdss, s1);
    float s2 = Gsod * Gsod;
    s2 = fmaf(Gsdo, Gsdo, s2);
    s2 = fmaf(Gosd, Gosd, s2);
    s2 = fmaf(Gods, Gods, s2);
    s2 = fmaf(Gdso, Gdso, s2);
    s2 = fmaf(Gdos, Gdos, s2);
    float s = fmaf(2.f, s2, s1) + 1e-12f;
    return 0.5f * (s * rsqrtf(s));   // 0.5 * sqrt(s)
}

__global__ __launch_bounds__(NTHREADS, 4)
void gme_kernel(const float* __restrict__ Y, const float* __restrict__ P,
                float* __restrict__ out, int out_n) {
    __shared__ float sm[2 * PAIR];          // 2 pairs x 2 planes x 2 volumes
    __shared__ float wsum[NTHREADS / 32];

    int lane = threadIdx.x;            // 0..31
    int ty = threadIdx.y;              // 0..7
    int tid = ty * 32 + lane;
    int vol = lane >> 4;               // 0 = Y, 1 = P
    int lx = lane & 15;
    int x0 = blockIdx.x * TVX;
    int y0 = blockIdx.y * TVY;
    int zb = blockIdx.z;
    int b = zb >> 2;                   // 4 z-chunks per batch
    int z0 = (zb & 3) * ZC;
    const float* Yb = Y + (long)b * 2 * CS;
    const float* Pb = P + (long)b * 2 * CS;

    // ---- plane-invariant halo addressing ----
    int v0 = (tid >= NSLOT) ? 1 : 0;
    int r0i = tid - v0 * NSLOT;
    int yy0 = r0i / ROWL, xx0 = r0i - yy0 * ROWL;
    int gy0 = y0 + yy0 - 1, gx0 = x0 + xx0 - 1;
    bool m0 = ((unsigned)gy0 < NDIM) && ((unsigned)gx0 < NDIM);
    const float* bp0 = (v0 ? Pb : Yb) + (m0 ? gy0 * NDIM + gx0 : 0);
    int si0 = v0 * VSTR + r0i;

    bool has1 = (tid < TOTSLOT - NTHREADS);        // tid < 104
    int r1i = tid + (NTHREADS - NSLOT);            // tid + 76
    int yy1 = r1i / ROWL, xx1 = r1i - yy1 * ROWL;
    int gy1 = y0 + yy1 - 1, gx1 = x0 + xx1 - 1;
    bool m1 = has1 && ((unsigned)gy1 < NDIM) && ((unsigned)gx1 < NDIM);
    const float* bp1 = Pb + (m1 ? gy1 * NDIM + gx1 : 0);
    int si1 = VSTR + r1i;

    int hbase = vol * VSTR + ty * ROWL + lx;       // computeH anchor

    // rA0/rB0 = slot0/slot1 for plane j; rA1/rB1 = for plane j+1
    float rA0, rB0, rA1, rB1;

#define PREF2(zz) do {                                             \
        int _z = (zz);                                             \
        bool zin0 = ((unsigned)_z < NDIM);                         \
        bool zin1 = ((unsigned)(_z + 1) < NDIM);                   \
        int zo0 = _z * PLANE;                                      \
        int zo1 = zo0 + PLANE;                                     \
        rA0 = rA1 = rB0 = rB1 = 0.f;                               \
        if (zin0 & m0) rA0 = bp0[zo0] + bp0[zo0 + CS];             \
        if (zin1 & m0) rA1 = bp0[zo1] + bp0[zo1 + CS];             \
        if (zin0 & m1) rB0 = bp1[zo0] + bp1[zo0 + CS];             \
        if (zin1 & m1) rB1 = bp1[zo1] + bp1[zo1 + CS];             \
    } while (0)

    int cb = 0;                        // current pair base offset in sm

#define COMMIT() do {                                              \
        int nb = cb ^ PAIR;                                        \
        sm[nb + si0] = rA0;                                        \
        sm[nb + PBUF + si0] = rA1;                                 \
        if (has1) { sm[nb + si1] = rB0;                            \
                    sm[nb + PBUF + si1] = rB1; }                   \
        __syncthreads();                                           \
        cb = nb;                                                   \
    } while (0)

#define EMIT(A, B, C) do {                                         \
        float e = edgeFromH(A, B, C);                              \
        float eo = __shfl_xor_sync(0xffffffffu, e, 16);            \
        float dd = e - eo;                                         \
        acc = fmaf(dd, dd, acc);                                   \
    } while (0)

    // One step = 2 planes, 1 barrier, 2 emits (except prime).
#define STEP2E(Hc, Ha, Ea, Eb, zpre, DOPF) do {                    \
        COMMIT();                                                  \
        if (DOPF) PREF2(zpre);                                     \
        computeH(sm + cb, hbase, Hc);                              \
        EMIT(Ea, Eb, Hc);                                          \
        computeH(sm + cb + PBUF, hbase, Ha);                       \
        EMIT(Eb, Hc, Ha);                                          \
    } while (0)

    float HA[7], HB[7], HC[7];
    float acc = 0.f;

    // prime: planes (z0-1, z0) -> HA, HB; prefetch (z0+1, z0+2)
    PREF2(z0 - 1);
    COMMIT();
    PREF2(z0 + 1);
    computeH(sm + cb, hbase, HA);
    computeH(sm + cb + PBUF, hbase, HB);

    int zz = z0 + 3;
    // 16 emit-steps total: 5 iterations x 3 + 1 tail
    #pragma unroll 1
    for (int k = 0; k < 5; k++) {
        STEP2E(HC, HA, HA, HB, zz, 1); zz += 2;
        STEP2E(HB, HC, HC, HA, zz, 1); zz += 2;
        STEP2E(HA, HB, HB, HC, zz, 1); zz += 2;
    }
    STEP2E(HC, HA, HA, HB, 0, 0);      // planes (z0+31, z0+32), emits z0+30, z0+31

#undef STEP2E
#undef EMIT
#undef COMMIT
#undef PREF2

    // block reduction (both half-warps contribute dd^2 -> double-counted; fixed in mean)
    #pragma unroll
    for (int o = 16; o; o >>= 1)
        acc += __shfl_down_sync(0xffffffffu, acc, o);
    int l32 = tid & 31, wid = tid >> 5;
    if (l32 == 0) wsum[wid] = acc;
    __syncthreads();
    if (wid == 0) {
        float v = (l32 < NTHREADS / 32) ? wsum[l32] : 0.f;
        #pragma unroll
        for (int o = 4; o; o >>= 1)
            v += __shfl_down_sync(0xffffffffu, v, o);
        if (l32 == 0) {
            atomicAdd(&g_acc, (double)v);
            __threadfence();
            unsigned done = atomicAdd(&g_cnt, 1u);
            if (done == NBLOCKS - 1) {
                // mean over 2*128^3 outputs, /2 for the double count
                float m = (float)(g_acc / 8388608.0);
                for (int i = 0; i < out_n; i++) out[i] = m;
                g_acc = 0.0;
                __threadfence();
                g_cnt = 0u;
            }
        }
    }
}

extern "C" void kernel_launch(void* const* d_in, const int* in_sizes, int n_in,
                              void* d_out, int out_size) {
    const float* Y = (const float*)d_in[0];
    const float* P = (const float*)d_in[1];
    dim3 grid(NDIM / TVX, NDIM / TVY, (NDIM / ZC) * 2);  // 8 x 16 x 8 = 1024
    dim3 blk(32, 8);
    gme_kernel<<<grid, blk>>>(Y, P, (float*)d_out, out_size);
}

// round 13
// speedup vs baseline: 1.1312x; 1.1312x over previous
#include <cuda_runtime.h>

#define NDIM 128
#define PLANE 16384          // 128*128
#define CS 2097152           // 128^3 (channel stride)
#define TVX 32               // tile voxels in x (2 per thread)
#define TVY 8
#define ZC 16
#define ROWL 36              // TVX+2 = 34, padded to 36 (even, float2-friendly)
#define COLH 10              // TVY+2
#define NSLOT (ROWL*COLH)    // 360 per volume (incl 2 pad cols)
#define VSTR 368             // smem stride between volumes (==16 mod 32)
#define TOTSLOT (2*NSLOT)    // 720
#define NTHREADS 256
#define NBLOCKS 1024         // 4 * 16 * 16

__device__ double g_acc;          // zero-init at load; self-resetting
__device__ unsigned int g_cnt;    // ditto

// 2-voxel computeH: halo window rows base..base+2, cols 0..3 relative.
// s=[1,2,1], d=[-1,0,1], o=[1,1,1]
// H[0]=s_y d_x  H[1]=d_y s_x  H[2]=o_y d_x  H[3]=d_y o_x
// H[4]=s_y s_x  H[5]=o_y s_x  H[6]=s_y o_x
__device__ __forceinline__ void computeH2(const float* __restrict__ sm,
                                          int base, float* H0, float* H1) {
    const float* r0 = sm + base;
    const float* r1 = r0 + ROWL;
    const float* r2 = r1 + ROWL;
    float2 p00 = *(const float2*)(r0), p01 = *(const float2*)(r0 + 2);
    float2 p10 = *(const float2*)(r1), p11 = *(const float2*)(r1 + 2);
    float2 p20 = *(const float2*)(r2), p21 = *(const float2*)(r2 + 2);
    float a0[4] = {p00.x, p00.y, p01.x, p01.y};
    float a1[4] = {p10.x, p10.y, p11.x, p11.y};
    float a2[4] = {p20.x, p20.y, p21.x, p21.y};
    float sc[4], dc[4], oc[4];
    #pragma unroll
    for (int c = 0; c < 4; c++) {
        float t = a0[c] + a2[c];
        sc[c] = fmaf(2.f, a1[c], t);
        oc[c] = t + a1[c];
        dc[c] = a2[c] - a0[c];
    }
    {
        float ts = sc[0] + sc[2], td = dc[0] + dc[2], to = oc[0] + oc[2];
        H0[0] = sc[2] - sc[0];
        H0[1] = fmaf(2.f, dc[1], td);
        H0[2] = oc[2] - oc[0];
        H0[3] = td + dc[1];
        H0[4] = fmaf(2.f, sc[1], ts);
        H0[5] = fmaf(2.f, oc[1], to);
        H0[6] = ts + sc[1];
    }
    {
        float ts = sc[1] + sc[3], td = dc[1] + dc[3], to = oc[1] + oc[3];
        H1[0] = sc[3] - sc[1];
        H1[1] = fmaf(2.f, dc[2], td);
        H1[2] = oc[3] - oc[1];
        H1[3] = td + dc[2];
        H1[4] = fmaf(2.f, sc[2], ts);
        H1[5] = fmaf(2.f, oc[2], to);
        H1[6] = ts + sc[2];
    }
}

// Combine z-ring (A=z-1, B=z, C=z+1) into edge magnitude * 0.5 (C=2 channels).
__device__ __forceinline__ float edgeFromH(const float* A, const float* B, const float* C) {
    float t;
    t = A[0] + C[0];
    float Gssd = fmaf(2.f, B[0], t);
    float Gosd = t + B[0];
    t = A[1] + C[1];
    float Gsds = fmaf(2.f, B[1], t);
    float Gods = t + B[1];
    t = A[2] + C[2];
    float Gsod = fmaf(2.f, B[2], t);
    t = A[3] + C[3];
    float Gsdo = fmaf(2.f, B[3], t);
    float Gdss = C[4] - A[4];
    float Gdos = C[5] - A[5];
    float Gdso = C[6] - A[6];
    float s1 = Gssd * Gssd;
    s1 = fmaf(Gsds, Gsds, s1);
    s1 = fmaf(Gdss, Gdss, s1);
    float s2 = Gsod * Gsod;
    s2 = fmaf(Gsdo, Gsdo, s2);
    s2 = fmaf(Gosd, Gosd, s2);
    s2 = fmaf(Gods, Gods, s2);
    s2 = fmaf(Gdso, Gdso, s2);
    s2 = fmaf(Gdos, Gdos, s2);
    float s = fmaf(2.f, s2, s1) + 1e-12f;
    return 0.5f * (s * rsqrtf(s));   // 0.5 * sqrt(s)
}

__global__ __launch_bounds__(NTHREADS, 3)
void gme_kernel(const float* __restrict__ Y, const float* __restrict__ P,
                float* __restrict__ out, int out_n) {
    __shared__ float sm0[2 * VSTR];
    __shared__ float sm1[2 * VSTR];
    __shared__ float wsum[NTHREADS / 32];

    int lane = threadIdx.x;            // 0..31
    int ty = threadIdx.y;              // 0..7
    int tid = ty * 32 + lane;
    int vol = lane >> 4;               // 0 = Y, 1 = P
    int lx = lane & 15;                // voxel-pair index: x = x0 + 2*lx, +1
    int x0 = blockIdx.x * TVX;
    int y0 = blockIdx.y * TVY;
    int zb = blockIdx.z;
    int b = zb >> 3;                   // 8 z-chunks per batch
    int z0 = (zb & 7) * ZC;
    const float* Yb = Y + (long)b * 2 * CS;
    const float* Pb = P + (long)b * 2 * CS;

    // ---- plane-invariant halo addressing: 3 loader slots/thread ----
    // slot s covers linear index t = tid + s*256 over [0, 720)
#define SLOTSETUP(T, bp, mm, si) {                                     \
        int _t = (T);                                                  \
        int _v = (_t >= NSLOT) ? 1 : 0;                                \
        int _r = _t - _v * NSLOT;                                      \
        int _yy = _r / ROWL, _xx = _r - _yy * ROWL;                    \
        int _gy = y0 + _yy - 1, _gx = x0 + _xx - 1;                    \
        mm = (_xx < 34) && ((unsigned)_gy < NDIM) && ((unsigned)_gx < NDIM); \
        bp = (_v ? Pb : Yb) + (mm ? _gy * NDIM + _gx : 0);             \
        si = _v * VSTR + _r;                                           \
    }
    const float *bpA, *bpB, *bpC;
    bool mA, mB, mC;
    int siA, siB, siC;
    SLOTSETUP(tid, bpA, mA, siA);
    SLOTSETUP(tid + 256, bpB, mB, siB);
    bool hasC = (tid < TOTSLOT - 512);          // tid < 208
    {
        int tC = hasC ? (tid + 512) : 0;
        SLOTSETUP(tC, bpC, mC, siC);
        mC = mC && hasC;
    }
#undef SLOTSETUP

    int hbase = vol * VSTR + ty * ROWL + 2 * lx;   // computeH2 anchor

    float rA, rB, rC;

#define PREF(zz) do {                                              \
        int _z = (zz);                                             \
        bool zin = ((unsigned)_z < NDIM);                          \
        int zoff = _z * PLANE;                                     \
        rA = 0.f; rB = 0.f; rC = 0.f;                              \
        if (zin & mA) rA = bpA[zoff] + bpA[zoff + CS];             \
        if (zin & mB) rB = bpB[zoff] + bpB[zoff + CS];             \
        if (zin & mC) rC = bpC[zoff] + bpC[zoff + CS];             \
    } while (0)

    float *cS = sm0, *nS = sm1;

#define STEP(HH, zpre, DO_PF) do {                                 \
        nS[siA] = rA;                                              \
        nS[siB] = rB;                                              \
        if (hasC) nS[siC] = rC;                                    \
        __syncthreads();                                           \
        { float* t = cS; cS = nS; nS = t; }                        \
        if (DO_PF) PREF(zpre);                                     \
        computeH2(cS, hbase, HH, (HH) + 7);                        \
    } while (0)

#define EMIT(A, B, C) do {                                         \
        float e0 = edgeFromH(A, B, C);                             \
        float e1 = edgeFromH((A) + 7, (B) + 7, (C) + 7);           \
        float f0 = __shfl_xor_sync(0xffffffffu, e0, 16);           \
        float f1 = __shfl_xor_sync(0xffffffffu, e1, 16);           \
        float d0 = e0 - f0, d1 = e1 - f1;                          \
        acc = fmaf(d0, d0, acc);                                   \
        acc = fmaf(d1, d1, acc);                                   \
    } while (0)

    float HA[14], HB[14], HC[14];
    float acc = 0.f;

    PREF(z0 - 1);
    STEP(HA, z0, 1);
    STEP(HB, z0 + 1, 1);
    int zz = z0 + 2;
    // 16 emit-steps: 5 x 3 + 1 tail  (18 planes total for ZC=16)
    #pragma unroll 1
    for (int k = 0; k < 5; k++) {
        STEP(HC, zz, 1); EMIT(HA, HB, HC); zz++;
        STEP(HA, zz, 1); EMIT(HB, HC, HA); zz++;
        STEP(HB, zz, 1); EMIT(HC, HA, HB); zz++;
    }
    STEP(HC, 0, 0); EMIT(HA, HB, HC);

#undef STEP
#undef EMIT
#undef PREF

    // block reduction (each voxel's dd^2 counted once per half-warp -> x2; fixed in mean)
    #pragma unroll
    for (int o = 16; o; o >>= 1)
        acc += __shfl_down_sync(0xffffffffu, acc, o);
    int l32 = tid & 31, wid = tid >> 5;
    if (l32 == 0) wsum[wid] = acc;
    __syncthreads();
    if (wid == 0) {
        float v = (l32 < NTHREADS / 32) ? wsum[l32] : 0.f;
        #pragma unroll
        for (int o = 4; o; o >>= 1)
            v += __shfl_down_sync(0xffffffffu, v, o);
        if (l32 == 0) {
            atomicAdd(&g_acc, (double)v);
            __threadfence();
            unsigned done = atomicAdd(&g_cnt, 1u);
            if (done == NBLOCKS - 1) {
                // mean over 2*128^3 outputs, /2 for the double count
                float m = (float)(g_acc / 8388608.0);
                for (int i = 0; i < out_n; i++) out[i] = m;
                g_acc = 0.0;
                __threadfence();
                g_cnt = 0u;
            }
        }
    }
}

extern "C" void kernel_launch(void* const* d_in, const int* in_sizes, int n_in,
                              void* d_out, int out_size) {
    const float* Y = (const float*)d_in[0];
    const float* P = (const float*)d_in[1];
    dim3 grid(NDIM / TVX, NDIM / TVY, (NDIM / ZC) * 2);  // 4 x 16 x 16 = 1024
    dim3 blk(32, 8);
    gme_kernel<<<grid, blk>>>(Y, P, (float*)d_out, out_size);
}